// round 4
// baseline (speedup 1.0000x reference)
#include <cuda_runtime.h>
#include <math.h>

// Problem dims
#define Bn 32
#define Tn 64
#define Dn 63
#define En 256
#define Hn 1024
#define H3 3072
#define Vn 16000
#define BT (Bn*Tn)   // 2048
#define BD (Bn*Dn)   // 2016
#define KSPLIT 8

// ---------------- scratch (static device globals; no allocs) ----------------
__device__ float g_x[BT*En];
__device__ float g_y[BD*En];
__device__ float g_xz_enc[(size_t)BT*H3];
__device__ float g_xz_dec[(size_t)BD*H3];
__device__ float g_enc_out[(size_t)BT*Hn];
__device__ float g_dec_out[(size_t)BD*Hn];
__device__ float g_hA[Bn*Hn];
__device__ float g_hB[Bn*Hn];
__device__ float g_part[KSPLIT*Bn*H3];
__device__ float g_w1e[(size_t)BT*Hn];
__device__ float g_w2d[(size_t)BD*Hn];
__device__ float g_av[(size_t)BD*2*Hn];

// ---------------- embedding gather ----------------
__global__ void embed_kernel(const int* __restrict__ ids, const float* __restrict__ emb,
                             int srcT, int dstT, float* __restrict__ out) {
    int r = blockIdx.x;                 // 0 .. B*dstT-1
    int b = r / dstT, t = r % dstT;
    int id = ids[b * srcT + t];
    const float* src = emb + (size_t)id * En;
    float* dst = out + (size_t)r * En;
    for (int i = threadIdx.x; i < En; i += blockDim.x) dst[i] = src[i];
}

// ---------------- tiled SGEMM: C[M,N] = A[M,K] @ B[K,N] (+bias[N]) ----------
// BM=128, BN=128, BK=8, 256 threads, 8x8 microtile, register-prefetch
// double buffering of global loads. Requires N%128==0, K%8==0. M guarded.
__global__ __launch_bounds__(256) void sgemm128(const float* __restrict__ A,
                                                const float* __restrict__ B,
                                                const float* __restrict__ bias,
                                                float* __restrict__ C,
                                                int M, int N, int K) {
    __shared__ float As[8][132];   // k-major; pad 132 -> conflict-free scalar STS
    __shared__ float Bs[8][128];
    int tid = threadIdx.x;
    int m0 = blockIdx.y * 128;
    int n0 = blockIdx.x * 128;
    int tm = (tid >> 4) * 8;
    int tn = (tid & 15) * 8;

    int lam = tid >> 1;            // A load: row within tile (0..127)
    int lak = (tid & 1) * 4;       // A load: k offset (0 or 4)
    int lbk = tid >> 5;            // B load: k (0..7)
    int lbn = (tid & 31) * 4;      // B load: n offset
    int gm  = m0 + lam;

    float acc[8][8];
#pragma unroll
    for (int i = 0; i < 8; i++)
#pragma unroll
        for (int j = 0; j < 8; j++) acc[i][j] = 0.f;

    // prefetch tile 0
    float4 pa = make_float4(0.f, 0.f, 0.f, 0.f);
    if (gm < M) pa = *(const float4*)&A[(size_t)gm * K + lak];
    float4 pb = *(const float4*)&B[(size_t)lbk * N + (n0 + lbn)];

    for (int k0 = 0; k0 < K; k0 += 8) {
        As[lak + 0][lam] = pa.x;
        As[lak + 1][lam] = pa.y;
        As[lak + 2][lam] = pa.z;
        As[lak + 3][lam] = pa.w;
        *(float4*)&Bs[lbk][lbn] = pb;
        __syncthreads();

        // prefetch next tile into registers while computing this one
        int kn = k0 + 8;
        if (kn < K) {
            if (gm < M) pa = *(const float4*)&A[(size_t)gm * K + (kn + lak)];
            pb = *(const float4*)&B[(size_t)(kn + lbk) * N + (n0 + lbn)];
        }

#pragma unroll
        for (int kk = 0; kk < 8; kk++) {
            float a[8], b[8];
            *(float4*)&a[0] = *(const float4*)&As[kk][tm];
            *(float4*)&a[4] = *(const float4*)&As[kk][tm + 4];
            *(float4*)&b[0] = *(const float4*)&Bs[kk][tn];
            *(float4*)&b[4] = *(const float4*)&Bs[kk][tn + 4];
#pragma unroll
            for (int i = 0; i < 8; i++)
#pragma unroll
                for (int j = 0; j < 8; j++)
                    acc[i][j] = fmaf(a[i], b[j], acc[i][j]);
        }
        __syncthreads();
    }
#pragma unroll
    for (int i = 0; i < 8; i++) {
        int gmo = m0 + tm + i;
        if (gmo >= M) continue;
        float* crow = C + (size_t)gmo * N + n0 + tn;
        if (bias) {
#pragma unroll
            for (int j = 0; j < 8; j++) acc[i][j] += bias[n0 + tn + j];
        }
        *(float4*)&crow[0] = *(float4*)&acc[i][0];
        *(float4*)&crow[4] = *(float4*)&acc[i][4];
    }
}

// ---------------- GRU step, phase 1: h @ Wh partial GEMM ----------------
// grid (24, KSPLIT): block (nb, ks) computes part[ks][0..31][n0..n0+127]
// = sum over k in [ks*128, ks*128+128) of h[m][k] * Wh[k][n].
// Wh read ONCE per step chip-wide (12.6 MB), reused across all 32 batches.
__global__ __launch_bounds__(256) void gru_gemm(const float* __restrict__ Wh, int t) {
    const float* h = (t & 1) ? g_hB : g_hA;
    int n0  = blockIdx.x * 128;
    int ks  = blockIdx.y;
    int k0g = ks * 128;
    __shared__ float sh[128][36];   // sh[k][m]; row = 144B (16B aligned -> LDS.128)
    __shared__ float sw[16][128];
    int tid = threadIdx.x;

#pragma unroll
    for (int l = 0; l < 16; l++) {
        int idx = tid + l * 256;
        int k = idx & 127, m = idx >> 7;
        sh[k][m] = h[m * Hn + k0g + k];
    }

    float acc[4][4];
#pragma unroll
    for (int i = 0; i < 4; i++)
#pragma unroll
        for (int j = 0; j < 4; j++) acc[i][j] = 0.f;

    int m0 = (tid & 7) * 4;        // 16B aligned into sh row
    int nt = (tid >> 3) * 4;       // 16B aligned into sw row

    for (int kc = 0; kc < 128; kc += 16) {
        __syncthreads();
#pragma unroll
        for (int l = 0; l < 2; l++) {
            int i4 = tid + l * 256;          // 0..511
            int k = i4 >> 5, n4 = (i4 & 31) * 4;
            *(float4*)&sw[k][n4] =
                *(const float4*)&Wh[(size_t)(k0g + kc + k) * H3 + n0 + n4];
        }
        __syncthreads();
#pragma unroll
        for (int kk = 0; kk < 16; kk++) {
            float4 av = *(const float4*)&sh[kc + kk][m0];
            float4 bv = *(const float4*)&sw[kk][nt];
            acc[0][0] = fmaf(av.x, bv.x, acc[0][0]); acc[0][1] = fmaf(av.x, bv.y, acc[0][1]);
            acc[0][2] = fmaf(av.x, bv.z, acc[0][2]); acc[0][3] = fmaf(av.x, bv.w, acc[0][3]);
            acc[1][0] = fmaf(av.y, bv.x, acc[1][0]); acc[1][1] = fmaf(av.y, bv.y, acc[1][1]);
            acc[1][2] = fmaf(av.y, bv.z, acc[1][2]); acc[1][3] = fmaf(av.y, bv.w, acc[1][3]);
            acc[2][0] = fmaf(av.z, bv.x, acc[2][0]); acc[2][1] = fmaf(av.z, bv.y, acc[2][1]);
            acc[2][2] = fmaf(av.z, bv.z, acc[2][2]); acc[2][3] = fmaf(av.z, bv.w, acc[2][3]);
            acc[3][0] = fmaf(av.w, bv.x, acc[3][0]); acc[3][1] = fmaf(av.w, bv.y, acc[3][1]);
            acc[3][2] = fmaf(av.w, bv.z, acc[3][2]); acc[3][3] = fmaf(av.w, bv.w, acc[3][3]);
        }
    }
#pragma unroll
    for (int i = 0; i < 4; i++) {
        int m = m0 + i;
        *(float4*)&g_part[(size_t)(ks * Bn + m) * H3 + n0 + nt] = *(float4*)&acc[i][0];
    }
}

// ---------------- GRU step, phase 2: reduce partials + gate math ------------
__global__ void gru_gate(const float* __restrict__ xz, float* __restrict__ out,
                         int steps, int t) {
    const float* hc = (t & 1) ? g_hB : g_hA;
    float* hn       = (t & 1) ? g_hA : g_hB;
    int b = blockIdx.y;
    int j = blockIdx.x * 256 + threadIdx.x;   // 0..1023

    float az = 0.f, ar = 0.f, ah = 0.f;
#pragma unroll
    for (int ks = 0; ks < KSPLIT; ks++) {
        const float* p = &g_part[(size_t)(ks * Bn + b) * H3];
        az += p[j];
        ar += p[j + Hn];
        ah += p[j + 2 * Hn];
    }
    const float* xt = xz + ((size_t)b * steps + t) * H3;
    float z  = 1.f / (1.f + expf(-(xt[j] + az)));
    float r  = 1.f / (1.f + expf(-(xt[j + Hn] + ar)));
    float hh = tanhf(xt[j + 2 * Hn] + r * ah);
    float v  = z * hc[b * Hn + j] + (1.f - z) * hh;
    hn[b * Hn + j] = v;
    out[((size_t)b * steps + t) * Hn + j] = v;
}

// ---------------- fused attention ----------------
// One block per (b,d). V_b is a uniform pre-softmax shift -> softmax-invariant.
__global__ void attn_kernel(const float* __restrict__ Vw,
                            float* __restrict__ av_out) {
    int bd = blockIdx.x;           // 0 .. BD-1
    int b = bd / Dn;
    __shared__ float s_w2d[Hn];
    __shared__ float s_sc[Tn];
    __shared__ float s_attn[Tn];
    int tid = threadIdx.x, warp = tid >> 5, lane = tid & 31;

    for (int i = tid; i < Hn; i += 256) s_w2d[i] = g_w2d[(size_t)bd * Hn + i];
    __syncthreads();

#pragma unroll
    for (int q = 0; q < 8; q++) {
        int e = warp * 8 + q;
        const float* w1 = g_w1e + ((size_t)b * Tn + e) * Hn;
        float s = 0.f;
        for (int k = lane; k < Hn; k += 32)
            s += tanhf(w1[k] + s_w2d[k]) * Vw[k];
#pragma unroll
        for (int o = 16; o > 0; o >>= 1) s += __shfl_down_sync(0xffffffffu, s, o);
        if (lane == 0) s_sc[e] = s;
    }
    __syncthreads();

    if (warp == 0) {
        float v0 = s_sc[lane], v1 = s_sc[lane + 32];
        float mx = fmaxf(v0, v1);
#pragma unroll
        for (int o = 16; o > 0; o >>= 1) mx = fmaxf(mx, __shfl_xor_sync(0xffffffffu, mx, o));
        float e0 = expf(v0 - mx), e1 = expf(v1 - mx);
        float ss = e0 + e1;
#pragma unroll
        for (int o = 16; o > 0; o >>= 1) ss += __shfl_xor_sync(0xffffffffu, ss, o);
        float inv = 1.f / ss;
        s_attn[lane] = e0 * inv;
        s_attn[lane + 32] = e1 * inv;
    }
    __syncthreads();

    for (int j = tid; j < Hn; j += 256) {
        float c = 0.f;
#pragma unroll 8
        for (int e = 0; e < Tn; e++)
            c += s_attn[e] * g_enc_out[((size_t)b * Tn + e) * Hn + j];
        av_out[(size_t)bd * 2 * Hn + j] = tanhf(c);
    }
    for (int j = tid; j < Hn; j += 256) {
        av_out[(size_t)bd * 2 * Hn + Hn + j] = tanhf(g_dec_out[(size_t)bd * Hn + j]);
    }
}

__global__ void zero_kernel(float* p, int n) {
    int i = blockIdx.x * blockDim.x + threadIdx.x;
    if (i < n) p[i] = 0.f;
}

// ---------------- launch ----------------
extern "C" void kernel_launch(void* const* d_in, const int* in_sizes, int n_in,
                              void* d_out, int out_size) {
    const int*   input_ids  = (const int*)d_in[0];
    const int*   target_ids = (const int*)d_in[1];
    const float* emb_enc    = (const float*)d_in[2];
    const float* emb_dec    = (const float*)d_in[3];
    const float* enc_Wx     = (const float*)d_in[4];
    const float* enc_Wh     = (const float*)d_in[5];
    const float* enc_b      = (const float*)d_in[6];
    const float* dec_Wx     = (const float*)d_in[7];
    const float* dec_Wh     = (const float*)d_in[8];
    const float* dec_b      = (const float*)d_in[9];
    const float* W1         = (const float*)d_in[10];
    const float* W2         = (const float*)d_in[11];
    const float* V_w        = (const float*)d_in[12];
    // d_in[13] = V_b : softmax-invariant, unused
    const float* Wp         = (const float*)d_in[14];
    const float* bp         = (const float*)d_in[15];
    float* logits = (float*)d_out;

    float *p_x, *p_y, *p_xze, *p_xzd, *p_eo, *p_do, *p_hA, *p_w1e, *p_w2d, *p_av;
    cudaGetSymbolAddress((void**)&p_x,   g_x);
    cudaGetSymbolAddress((void**)&p_y,   g_y);
    cudaGetSymbolAddress((void**)&p_xze, g_xz_enc);
    cudaGetSymbolAddress((void**)&p_xzd, g_xz_dec);
    cudaGetSymbolAddress((void**)&p_eo,  g_enc_out);
    cudaGetSymbolAddress((void**)&p_do,  g_dec_out);
    cudaGetSymbolAddress((void**)&p_hA,  g_hA);
    cudaGetSymbolAddress((void**)&p_w1e, g_w1e);
    cudaGetSymbolAddress((void**)&p_w2d, g_w2d);
    cudaGetSymbolAddress((void**)&p_av,  g_av);

    // h0 = 0 for encoder
    zero_kernel<<<(Bn * Hn + 255) / 256, 256>>>(p_hA, Bn * Hn);

    // embeddings
    embed_kernel<<<BT, 256>>>(input_ids,  emb_enc, Tn, Tn, p_x);
    embed_kernel<<<BD, 256>>>(target_ids, emb_dec, Tn, Dn, p_y);

    // input projections xz = x @ Wx + b
    sgemm128<<<dim3(H3 / 128, (BT + 127) / 128), 256>>>(p_x, enc_Wx, enc_b, p_xze, BT, H3, En);
    sgemm128<<<dim3(H3 / 128, (BD + 127) / 128), 256>>>(p_y, dec_Wx, dec_b, p_xzd, BD, H3, En);

    // encoder recurrence (final state lands in g_hA after 64 steps)
    for (int t = 0; t < Tn; t++) {
        gru_gemm<<<dim3(H3 / 128, KSPLIT), 256>>>(enc_Wh, t);
        gru_gate<<<dim3(4, Bn), 256>>>(p_xze, p_eo, Tn, t);
    }

    // decoder recurrence (starts from g_hA = encoder final state)
    for (int t = 0; t < Dn; t++) {
        gru_gemm<<<dim3(H3 / 128, KSPLIT), 256>>>(dec_Wh, t);
        gru_gate<<<dim3(4, Bn), 256>>>(p_xzd, p_do, Dn, t);
    }

    // attention projections
    sgemm128<<<dim3(Hn / 128, (BT + 127) / 128), 256>>>(p_eo, W1, nullptr, p_w1e, BT, Hn, Hn);
    sgemm128<<<dim3(Hn / 128, (BD + 127) / 128), 256>>>(p_do, W2, nullptr, p_w2d, BD, Hn, Hn);

    // fused attention -> attention vector
    attn_kernel<<<BD, 256>>>(V_w, p_av);

    // output projection logits = av @ Wp + bp
    sgemm128<<<dim3(Vn / 128, (BD + 127) / 128), 256>>>(p_av, Wp, bp, logits, BD, Vn, 2 * Hn);
}

// round 16
// speedup vs baseline: 1.5942x; 1.5942x over previous
#include <cuda_runtime.h>
#include <math.h>
#include <stdint.h>

// Problem dims
#define Bn 32
#define Tn 64
#define Dn 63
#define En 256
#define Hn 1024
#define H3 3072
#define Vn 16000
#define BT (Bn*Tn)   // 2048
#define BD (Bn*Dn)   // 2016
#define KSPLIT 8

// ---------------- scratch (static device globals; no allocs) ----------------
__device__ float g_x[BT*En];
__device__ float g_y[BD*En];
__device__ float g_xz_enc[(size_t)BT*H3];
__device__ float g_xz_dec[(size_t)BD*H3];
__device__ float g_enc_out[(size_t)BT*Hn];
__device__ float g_dec_out[(size_t)BD*Hn];
__device__ float g_hA[Bn*Hn];
__device__ float g_hB[Bn*Hn];
__device__ float g_part[KSPLIT*Bn*H3];
__device__ float g_w1e[(size_t)BT*Hn];
__device__ float g_w2d[(size_t)BD*Hn];
__device__ float g_av[(size_t)BD*2*Hn];

// ---------------- helpers ----------------
__device__ __forceinline__ float tf32r(float x) {
    uint32_t u;
    asm("cvt.rna.tf32.f32 %0, %1;" : "=r"(u) : "f"(x));
    return __uint_as_float(u);
}

__device__ __forceinline__ void mma_tf32(float* d, const uint32_t* a, const uint32_t* b) {
    asm volatile(
        "mma.sync.aligned.m16n8k8.row.col.f32.tf32.tf32.f32 "
        "{%0,%1,%2,%3}, {%4,%5,%6,%7}, {%8,%9}, {%0,%1,%2,%3};"
        : "+f"(d[0]), "+f"(d[1]), "+f"(d[2]), "+f"(d[3])
        : "r"(a[0]), "r"(a[1]), "r"(a[2]), "r"(a[3]), "r"(b[0]), "r"(b[1]));
}

// ---------------- embedding gather ----------------
__global__ void embed_kernel(const int* __restrict__ ids, const float* __restrict__ emb,
                             int srcT, int dstT, float* __restrict__ out) {
    int r = blockIdx.x;                 // 0 .. B*dstT-1
    int b = r / dstT, t = r % dstT;
    int id = ids[b * srcT + t];
    const float* src = emb + (size_t)id * En;
    float* dst = out + (size_t)r * En;
    for (int i = threadIdx.x; i < En; i += blockDim.x) dst[i] = src[i];
}

// ---------------- tf32 tensor-core GEMM -------------------------------------
// C[M,N] = A[M,K] @ B[K,N] (+bias). A,B,C row-major fp32; compute in tf32 MMA
// with fp32 accumulation. 128x128 block tile, BK=16, 256 threads = 8 warps in
// 2x4 grid, each warp a 64x32 tile = 4x4 m16n8k8 fragments.
// Requires N%128==0, K%16==0; M guarded.
__global__ __launch_bounds__(256) void tf32gemm(const float* __restrict__ A,
                                                const float* __restrict__ B,
                                                const float* __restrict__ bias,
                                                float* __restrict__ C,
                                                int M, int N, int K) {
    __shared__ float As[128][20];   // m-major, tf32-rounded; bank(20g+tig) covers 0..31
    __shared__ float Bs[128][21];   // n-major, tf32-rounded; bank(21n+k) conflict-free
    int tid  = threadIdx.x;
    int warp = tid >> 5, lane = tid & 31;
    int g = lane >> 2, tig = lane & 3;
    int m0 = blockIdx.y * 128, n0 = blockIdx.x * 128;
    int wm = (warp >> 2) * 64;      // 0 / 64
    int wn = (warp & 3) * 32;       // 0,32,64,96

    float acc[4][4][4];
#pragma unroll
    for (int mi = 0; mi < 4; mi++)
#pragma unroll
        for (int ni = 0; ni < 4; ni++)
#pragma unroll
            for (int r = 0; r < 4; r++) acc[mi][ni][r] = 0.f;

    // global-load ownership
    int am = tid >> 2;              // A rows am, am+64
    int ak = (tid & 3) * 4;         // A k quad
    int bk = tid >> 5;              // B rows bk, bk+8
    int bn = (tid & 31) * 4;        // B n quad

    const float4 z4 = make_float4(0.f, 0.f, 0.f, 0.f);
    float4 pa0 = z4, pa1 = z4, pb0, pb1;
    if (m0 + am      < M) pa0 = *(const float4*)&A[(size_t)(m0 + am)      * K + ak];
    if (m0 + am + 64 < M) pa1 = *(const float4*)&A[(size_t)(m0 + am + 64) * K + ak];
    pb0 = *(const float4*)&B[(size_t)bk       * N + (n0 + bn)];
    pb1 = *(const float4*)&B[(size_t)(bk + 8) * N + (n0 + bn)];

    for (int k0 = 0; k0 < K; k0 += 16) {
        // stage (tf32-rounded) into smem
        As[am][ak + 0] = tf32r(pa0.x); As[am][ak + 1] = tf32r(pa0.y);
        As[am][ak + 2] = tf32r(pa0.z); As[am][ak + 3] = tf32r(pa0.w);
        As[am + 64][ak + 0] = tf32r(pa1.x); As[am + 64][ak + 1] = tf32r(pa1.y);
        As[am + 64][ak + 2] = tf32r(pa1.z); As[am + 64][ak + 3] = tf32r(pa1.w);
        Bs[bn + 0][bk] = tf32r(pb0.x); Bs[bn + 1][bk] = tf32r(pb0.y);
        Bs[bn + 2][bk] = tf32r(pb0.z); Bs[bn + 3][bk] = tf32r(pb0.w);
        Bs[bn + 0][bk + 8] = tf32r(pb1.x); Bs[bn + 1][bk + 8] = tf32r(pb1.y);
        Bs[bn + 2][bk + 8] = tf32r(pb1.z); Bs[bn + 3][bk + 8] = tf32r(pb1.w);
        __syncthreads();

        // prefetch next K-slice
        int kn = k0 + 16;
        if (kn < K) {
            pa0 = z4; pa1 = z4;
            if (m0 + am      < M) pa0 = *(const float4*)&A[(size_t)(m0 + am)      * K + kn + ak];
            if (m0 + am + 64 < M) pa1 = *(const float4*)&A[(size_t)(m0 + am + 64) * K + kn + ak];
            pb0 = *(const float4*)&B[(size_t)(kn + bk)     * N + (n0 + bn)];
            pb1 = *(const float4*)&B[(size_t)(kn + bk + 8) * N + (n0 + bn)];
        }

#pragma unroll
        for (int kk = 0; kk < 16; kk += 8) {
            uint32_t af[4][4], bf[4][2];
#pragma unroll
            for (int mi = 0; mi < 4; mi++) {
                int r0 = wm + mi * 16 + g;
                af[mi][0] = __float_as_uint(As[r0][kk + tig]);
                af[mi][1] = __float_as_uint(As[r0 + 8][kk + tig]);
                af[mi][2] = __float_as_uint(As[r0][kk + tig + 4]);
                af[mi][3] = __float_as_uint(As[r0 + 8][kk + tig + 4]);
            }
#pragma unroll
            for (int ni = 0; ni < 4; ni++) {
                int c0 = wn + ni * 8 + g;
                bf[ni][0] = __float_as_uint(Bs[c0][kk + tig]);
                bf[ni][1] = __float_as_uint(Bs[c0][kk + tig + 4]);
            }
#pragma unroll
            for (int mi = 0; mi < 4; mi++)
#pragma unroll
                for (int ni = 0; ni < 4; ni++)
                    mma_tf32(acc[mi][ni], af[mi], bf[ni]);
        }
        __syncthreads();
    }

    // epilogue: c0:(g,2tig) c1:(g,2tig+1) c2:(g+8,2tig) c3:(g+8,2tig+1)
#pragma unroll
    for (int mi = 0; mi < 4; mi++) {
#pragma unroll
        for (int ni = 0; ni < 4; ni++) {
            int row = m0 + wm + mi * 16 + g;
            int col = n0 + wn + ni * 8 + tig * 2;
            float b0 = bias ? bias[col] : 0.f;
            float b1 = bias ? bias[col + 1] : 0.f;
            if (row < M) {
                C[(size_t)row * N + col]     = acc[mi][ni][0] + b0;
                C[(size_t)row * N + col + 1] = acc[mi][ni][1] + b1;
            }
            if (row + 8 < M) {
                C[(size_t)(row + 8) * N + col]     = acc[mi][ni][2] + b0;
                C[(size_t)(row + 8) * N + col + 1] = acc[mi][ni][3] + b1;
            }
        }
    }
}

// ---------------- GRU step, phase 1: h @ Wh partial GEMM (fp32) ------------
// grid (24, KSPLIT). Wh read ONCE per step chip-wide; reused across batches.
__global__ __launch_bounds__(256) void gru_gemm(const float* __restrict__ Wh, int t) {
    const float* h = (t & 1) ? g_hB : g_hA;
    int n0  = blockIdx.x * 128;
    int ks  = blockIdx.y;
    int k0g = ks * 128;
    __shared__ float sh[128][36];   // sh[k][m]; row = 144B (16B aligned -> LDS.128)
    __shared__ float sw[16][128];
    int tid = threadIdx.x;

#pragma unroll
    for (int l = 0; l < 16; l++) {
        int idx = tid + l * 256;
        int k = idx & 127, m = idx >> 7;
        sh[k][m] = h[m * Hn + k0g + k];
    }

    float acc[4][4];
#pragma unroll
    for (int i = 0; i < 4; i++)
#pragma unroll
        for (int j = 0; j < 4; j++) acc[i][j] = 0.f;

    int m0 = (tid & 7) * 4;
    int nt = (tid >> 3) * 4;

    for (int kc = 0; kc < 128; kc += 16) {
        __syncthreads();
#pragma unroll
        for (int l = 0; l < 2; l++) {
            int i4 = tid + l * 256;
            int k = i4 >> 5, n4 = (i4 & 31) * 4;
            *(float4*)&sw[k][n4] =
                *(const float4*)&Wh[(size_t)(k0g + kc + k) * H3 + n0 + n4];
        }
        __syncthreads();
#pragma unroll
        for (int kk = 0; kk < 16; kk++) {
            float4 av = *(const float4*)&sh[kc + kk][m0];
            float4 bv = *(const float4*)&sw[kk][nt];
            acc[0][0] = fmaf(av.x, bv.x, acc[0][0]); acc[0][1] = fmaf(av.x, bv.y, acc[0][1]);
            acc[0][2] = fmaf(av.x, bv.z, acc[0][2]); acc[0][3] = fmaf(av.x, bv.w, acc[0][3]);
            acc[1][0] = fmaf(av.y, bv.x, acc[1][0]); acc[1][1] = fmaf(av.y, bv.y, acc[1][1]);
            acc[1][2] = fmaf(av.y, bv.z, acc[1][2]); acc[1][3] = fmaf(av.y, bv.w, acc[1][3]);
            acc[2][0] = fmaf(av.z, bv.x, acc[2][0]); acc[2][1] = fmaf(av.z, bv.y, acc[2][1]);
            acc[2][2] = fmaf(av.z, bv.z, acc[2][2]); acc[2][3] = fmaf(av.z, bv.w, acc[2][3]);
            acc[3][0] = fmaf(av.w, bv.x, acc[3][0]); acc[3][1] = fmaf(av.w, bv.y, acc[3][1]);
            acc[3][2] = fmaf(av.w, bv.z, acc[3][2]); acc[3][3] = fmaf(av.w, bv.w, acc[3][3]);
        }
    }
#pragma unroll
    for (int i = 0; i < 4; i++) {
        int m = m0 + i;
        *(float4*)&g_part[(size_t)(ks * Bn + m) * H3 + n0 + nt] = *(float4*)&acc[i][0];
    }
}

// ---------------- GRU step, phase 2: reduce partials + gate math ------------
// grid (Bn) x 1024 threads: block = one batch row, thread = one hidden column.
__global__ __launch_bounds__(1024) void gru_gate(const float* __restrict__ xz,
                                                 float* __restrict__ out,
                                                 int steps, int t) {
    const float* hc = (t & 1) ? g_hB : g_hA;
    float* hn       = (t & 1) ? g_hA : g_hB;
    int b = blockIdx.x;
    int j = threadIdx.x;                      // 0..1023

    float az = 0.f, ar = 0.f, ah = 0.f;
#pragma unroll
    for (int ks = 0; ks < KSPLIT; ks++) {
        const float* p = &g_part[(size_t)(ks * Bn + b) * H3];
        az += p[j];
        ar += p[j + Hn];
        ah += p[j + 2 * Hn];
    }
    const float* xt = xz + ((size_t)b * steps + t) * H3;
    float z  = 1.f / (1.f + expf(-(xt[j] + az)));
    float r  = 1.f / (1.f + expf(-(xt[j + Hn] + ar)));
    float hh = tanhf(xt[j + 2 * Hn] + r * ah);
    float v  = z * hc[b * Hn + j] + (1.f - z) * hh;
    hn[b * Hn + j] = v;
    out[((size_t)b * steps + t) * Hn + j] = v;
}

// ---------------- fused attention ----------------
// One block per (b,d). V_b is a uniform pre-softmax shift -> softmax-invariant.
__global__ void attn_kernel(const float* __restrict__ Vw,
                            float* __restrict__ av_out) {
    int bd = blockIdx.x;           // 0 .. BD-1
    int b = bd / Dn;
    __shared__ float s_w2d[Hn];
    __shared__ float s_sc[Tn];
    __shared__ float s_attn[Tn];
    int tid = threadIdx.x, warp = tid >> 5, lane = tid & 31;

    for (int i = tid; i < Hn; i += 256) s_w2d[i] = g_w2d[(size_t)bd * Hn + i];
    __syncthreads();

#pragma unroll
    for (int q = 0; q < 8; q++) {
        int e = warp * 8 + q;
        const float* w1 = g_w1e + ((size_t)b * Tn + e) * Hn;
        float s = 0.f;
        for (int k = lane; k < Hn; k += 32)
            s += tanhf(w1[k] + s_w2d[k]) * Vw[k];
#pragma unroll
        for (int o = 16; o > 0; o >>= 1) s += __shfl_down_sync(0xffffffffu, s, o);
        if (lane == 0) s_sc[e] = s;
    }
    __syncthreads();

    if (warp == 0) {
        float v0 = s_sc[lane], v1 = s_sc[lane + 32];
        float mx = fmaxf(v0, v1);
#pragma unroll
        for (int o = 16; o > 0; o >>= 1) mx = fmaxf(mx, __shfl_xor_sync(0xffffffffu, mx, o));
        float e0 = expf(v0 - mx), e1 = expf(v1 - mx);
        float ss = e0 + e1;
#pragma unroll
        for (int o = 16; o > 0; o >>= 1) ss += __shfl_xor_sync(0xffffffffu, ss, o);
        float inv = 1.f / ss;
        s_attn[lane] = e0 * inv;
        s_attn[lane + 32] = e1 * inv;
    }
    __syncthreads();

    for (int j = tid; j < Hn; j += 256) {
        float c = 0.f;
#pragma unroll 8
        for (int e = 0; e < Tn; e++)
            c += s_attn[e] * g_enc_out[((size_t)b * Tn + e) * Hn + j];
        av_out[(size_t)bd * 2 * Hn + j] = tanhf(c);
    }
    for (int j = tid; j < Hn; j += 256) {
        av_out[(size_t)bd * 2 * Hn + Hn + j] = tanhf(g_dec_out[(size_t)bd * Hn + j]);
    }
}

__global__ void zero_kernel(float* p, int n) {
    int i = blockIdx.x * blockDim.x + threadIdx.x;
    if (i < n) p[i] = 0.f;
}

// ---------------- launch ----------------
extern "C" void kernel_launch(void* const* d_in, const int* in_sizes, int n_in,
                              void* d_out, int out_size) {
    const int*   input_ids  = (const int*)d_in[0];
    const int*   target_ids = (const int*)d_in[1];
    const float* emb_enc    = (const float*)d_in[2];
    const float* emb_dec    = (const float*)d_in[3];
    const float* enc_Wx     = (const float*)d_in[4];
    const float* enc_Wh     = (const float*)d_in[5];
    const float* enc_b      = (const float*)d_in[6];
    const float* dec_Wx     = (const float*)d_in[7];
    const float* dec_Wh     = (const float*)d_in[8];
    const float* dec_b      = (const float*)d_in[9];
    const float* W1         = (const float*)d_in[10];
    const float* W2         = (const float*)d_in[11];
    const float* V_w        = (const float*)d_in[12];
    // d_in[13] = V_b : softmax-invariant, unused
    const float* Wp         = (const float*)d_in[14];
    const float* bp         = (const float*)d_in[15];
    float* logits = (float*)d_out;

    float *p_x, *p_y, *p_xze, *p_xzd, *p_eo, *p_do, *p_hA, *p_w1e, *p_w2d, *p_av;
    cudaGetSymbolAddress((void**)&p_x,   g_x);
    cudaGetSymbolAddress((void**)&p_y,   g_y);
    cudaGetSymbolAddress((void**)&p_xze, g_xz_enc);
    cudaGetSymbolAddress((void**)&p_xzd, g_xz_dec);
    cudaGetSymbolAddress((void**)&p_eo,  g_enc_out);
    cudaGetSymbolAddress((void**)&p_do,  g_dec_out);
    cudaGetSymbolAddress((void**)&p_hA,  g_hA);
    cudaGetSymbolAddress((void**)&p_w1e, g_w1e);
    cudaGetSymbolAddress((void**)&p_w2d, g_w2d);
    cudaGetSymbolAddress((void**)&p_av,  g_av);

    // h0 = 0 for encoder
    zero_kernel<<<(Bn * Hn + 255) / 256, 256>>>(p_hA, Bn * Hn);

    // embeddings
    embed_kernel<<<BT, 256>>>(input_ids,  emb_enc, Tn, Tn, p_x);
    embed_kernel<<<BD, 256>>>(target_ids, emb_dec, Tn, Dn, p_y);

    // input projections xz = x @ Wx + b (tf32 tensor core)
    tf32gemm<<<dim3(H3 / 128, (BT + 127) / 128), 256>>>(p_x, enc_Wx, enc_b, p_xze, BT, H3, En);
    tf32gemm<<<dim3(H3 / 128, (BD + 127) / 128), 256>>>(p_y, dec_Wx, dec_b, p_xzd, BD, H3, En);

    // encoder recurrence (fp32, final state lands in g_hA after 64 steps)
    for (int t = 0; t < Tn; t++) {
        gru_gemm<<<dim3(H3 / 128, KSPLIT), 256>>>(enc_Wh, t);
        gru_gate<<<Bn, 1024>>>(p_xze, p_eo, Tn, t);
    }

    // decoder recurrence (starts from g_hA = encoder final state)
    for (int t = 0; t < Dn; t++) {
        gru_gemm<<<dim3(H3 / 128, KSPLIT), 256>>>(dec_Wh, t);
        gru_gate<<<Bn, 1024>>>(p_xzd, p_do, Dn, t);
    }

    // attention projections (tf32 tensor core)
    tf32gemm<<<dim3(Hn / 128, (BT + 127) / 128), 256>>>(p_eo, W1, nullptr, p_w1e, BT, Hn, Hn);
    tf32gemm<<<dim3(Hn / 128, (BD + 127) / 128), 256>>>(p_do, W2, nullptr, p_w2d, BD, Hn, Hn);

    // fused attention -> attention vector
    attn_kernel<<<BD, 256>>>(V_w, p_av);

    // output projection logits = av @ Wp + bp (tf32 tensor core)
    tf32gemm<<<dim3(Vn / 128, (BD + 127) / 128), 256>>>(p_av, Wp, bp, logits, BD, Vn, 2 * Hn);
}